// round 14
// baseline (speedup 1.0000x reference)
#include <cuda_runtime.h>
#include <cuda_bf16.h>
#include <mma.h>
#include <cstdint>

using namespace nvcuda;

#define Bn 16
#define Tn 12
#define BT 192          // B*T
#define Nn 325
#define Dd 64
#define Hh 4
#define Ee 2600
#define ET (Ee + Nn)    // 2925 edges incl. self loops
#define NBT (Nn * BT)   // 62400 (n,bt) pairs

typedef unsigned long long ull;

// ---------------- packed f32x2 helpers ----------------
__device__ __forceinline__ void ffma2(ull& d, ull a, ull b) {
    asm("fma.rn.f32x2 %0, %1, %2, %0;" : "+l"(d) : "l"(a), "l"(b));
}
__device__ __forceinline__ ull pack2(float lo, float hi) {
    ull r; asm("mov.b64 %0, {%1,%2};" : "=l"(r) : "f"(lo), "f"(hi)); return r;
}
__device__ __forceinline__ void unpack2(float& lo, float& hi, ull v) {
    asm("mov.b64 {%0,%1}, %2;" : "=f"(lo), "=f"(hi) : "l"(v));
}
__device__ __forceinline__ uint32_t smem_u32(const void* p) {
    uint32_t a;
    asm("{.reg .u64 t; cvta.to.shared.u64 t, %1; cvt.u32.u64 %0, t;}" : "=r"(a) : "l"(p));
    return a;
}
#define CP_CG16(dst_u32, src_ptr) \
    asm volatile("cp.async.cg.shared.global [%0], [%1], 16;" \
                 :: "r"(dst_u32), "l"(src_ptr) : "memory")
#define CP_CA16(dst_u32, src_ptr) \
    asm volatile("cp.async.ca.shared.global [%0], [%1], 16;" \
                 :: "r"(dst_u32), "l"(src_ptr) : "memory")
#define CP_COMMIT() asm volatile("cp.async.commit_group;" ::: "memory")

// ---------------- device scratch ----------------
__device__ __align__(16) float g_wsrc[Hh * Dd];
__device__ __align__(16) float g_wdst[Hh * Dd];
__device__ __align__(16) float g_asrc[NBT * Hh];
__device__ __align__(16) float g_adst[NBT * Hh];
__device__ int g_rowptr[Nn + 1];
__device__ int g_esrc[ET];
__device__ __align__(16) __nv_bfloat16 g_Ahi[(size_t)NBT * 256];  // 32MB
__device__ __align__(16) __nv_bfloat16 g_Alo[(size_t)NBT * 256];  // 32MB
__device__ __align__(16) __nv_bfloat16 g_Bh[256 * 64];            // B hi, [k][f], 1/H folded
__device__ __align__(16) __nv_bfloat16 g_Bl[256 * 64];            // B lo

// ---------------- K0: setup (block 0 = CSR, block 1 = weight prep) ----------------
// edge_index may be int32 or int64 (JAX x64-config). Probe: int64 => every odd
// 32-bit word in the first 5200 words is 0 (values < 325).
__global__ void k_setup(const int* __restrict__ ew,
                        const float* __restrict__ W,
                        const float* __restrict__ att_src,
                        const float* __restrict__ att_dst) {
    int tid = threadIdx.x;
    int bd = blockDim.x;      // 1024
    const unsigned full = 0xffffffffu;
    if (blockIdx.x == 1) {
        if (tid < 256) {
            int h = tid >> 6, d = tid & 63;
            float s1 = 0.f, s2 = 0.f;
            #pragma unroll 8
            for (int f = 0; f < 64; f++) {
                float w = W[(d * Hh + h) * 64 + f];
                s1 += w * att_src[h * 64 + f];
                s2 += w * att_dst[h * 64 + f];
            }
            g_wsrc[tid] = s1;
            g_wdst[tid] = s2;
        }
        for (int i = tid; i < 256 * 64; i += bd) {
            int k = i >> 6, f = i & 63;
            int h = k >> 6, d = k & 63;
            float w = W[(d * Hh + h) * 64 + f] * 0.25f;   // 1/H folded
            __nv_bfloat16 hi = __float2bfloat16(w);
            g_Bh[i] = hi;
            g_Bl[i] = __float2bfloat16(w - __bfloat162float(hi));
        }
        return;
    }
    // ---- CSR build, deterministic (sorted by original edge id) ----
    __shared__ int sdst[ET];
    __shared__ int ssrc[ET];
    __shared__ int sslot[ET];
    __shared__ int scnt[Nn + 1];
    __shared__ int scur[Nn];
    __shared__ int s_is32;
    if (tid == 0) s_is32 = 0;
    __syncthreads();
    for (int i = tid; i < Ee; i += bd)
        if (ew[2 * i + 1] != 0) s_is32 = 1;
    __syncthreads();
    int is32 = s_is32;
    for (int i = tid; i < ET; i += bd) {
        if (i < Ee) {
            if (is32) { ssrc[i] = ew[i];         sdst[i] = ew[Ee + i]; }
            else      { ssrc[i] = ew[2 * i];     sdst[i] = ew[2 * (Ee + i)]; }
        } else {
            ssrc[i] = i - Ee;
            sdst[i] = i - Ee;
        }
    }
    for (int i = tid; i <= Nn; i += bd) scnt[i] = 0;
    __syncthreads();
    for (int i = tid; i < ET; i += bd) atomicAdd(&scnt[sdst[i] + 1], 1);
    __syncthreads();
    if (tid < 32) {            // warp-parallel inclusive scan
        int carry = 0;
        for (int base = 0; base <= Nn; base += 32) {
            int i = base + tid;
            int v = (i <= Nn) ? scnt[i] : 0;
            #pragma unroll
            for (int o = 1; o < 32; o <<= 1) {
                int t = __shfl_up_sync(full, v, o);
                if (tid >= o) v += t;
            }
            v += carry;
            if (i <= Nn) scnt[i] = v;
            carry = __shfl_sync(full, v, 31);
        }
    }
    __syncthreads();
    for (int i = tid; i <= Nn; i += bd) g_rowptr[i] = scnt[i];
    for (int i = tid; i < Nn; i += bd) scur[i] = scnt[i];
    __syncthreads();
    for (int e = tid; e < ET; e += bd) {
        int pos = atomicAdd(&scur[sdst[e]], 1);
        sslot[pos] = e;
    }
    __syncthreads();
    for (int n = tid; n < Nn; n += bd) {
        int a = scnt[n], b = scnt[n + 1];
        for (int i = a + 1; i < b; i++) {      // sort by edge id -> deterministic
            int v = sslot[i];
            int j = i - 1;
            while (j >= a && sslot[j] > v) { sslot[j + 1] = sslot[j]; j--; }
            sslot[j + 1] = v;
        }
        for (int p = a; p < b; p++) g_esrc[p] = ssrc[sslot[p]];
    }
}

// ---------------- K1: attention logits, warp per (n,bt) ----------------
__global__ __launch_bounds__(256) void k_alpha(const float* __restrict__ x) {
    __shared__ float sw[512];
    int tid = threadIdx.x;
    sw[tid] = g_wsrc[tid];
    sw[256 + tid] = g_wdst[tid];
    __syncthreads();
    int gid = blockIdx.x * 8 + (tid >> 5);
    int lane = tid & 31;
    int n = gid / BT, bt = gid % BT;
    float2 xv = ((const float2*)(x + ((size_t)bt * Nn + n) * 64))[lane];
    float p[8];
    #pragma unroll
    for (int h = 0; h < 4; h++) {
        p[h]     = xv.x * sw[h * 64 + 2 * lane]       + xv.y * sw[h * 64 + 2 * lane + 1];
        p[4 + h] = xv.x * sw[256 + h * 64 + 2 * lane] + xv.y * sw[256 + h * 64 + 2 * lane + 1];
    }
    #pragma unroll
    for (int o = 16; o; o >>= 1) {
        #pragma unroll
        for (int j = 0; j < 8; j++) p[j] += __shfl_xor_sync(0xffffffffu, p[j], o);
    }
    int base = gid * 4;
    if (lane < 4) g_asrc[base + lane] = p[lane];
    else if (lane < 8) g_adst[base + lane - 4] = p[lane];
}

// ---------------- K2: segment softmax + aggregation -> bf16 hi/lo ----------------
__device__ __forceinline__ float lrelu(float v) { return v >= 0.f ? v : 0.2f * v; }

__device__ __forceinline__ void split_store(ull v, __nv_bfloat162* ah,
                                            __nv_bfloat162* al, int off) {
    float e, o; unpack2(e, o, v);
    __nv_bfloat16 he = __float2bfloat16(e), ho = __float2bfloat16(o);
    float re = e - __bfloat162float(he);
    float ro = o - __bfloat162float(ho);
    ah[off] = __halves2bfloat162(he, ho);
    al[off] = __halves2bfloat162(__float2bfloat16(re), __float2bfloat16(ro));
}

__global__ __launch_bounds__(256) void k_agg(const float* __restrict__ x) {
    __shared__ int s_src[8][32];
    __shared__ __align__(16) ull s_cf[8][32][4];   // dup'd coef pairs {c,c}
    const unsigned full = 0xffffffffu;
    int tid = threadIdx.x;
    int w = tid >> 5, lane = tid & 31;
    int gid = blockIdx.x * 8 + w;
    int n = gid / BT, bt = gid % BT;
    int rs = g_rowptr[n], re = g_rowptr[n + 1];
    float4 adv = *(const float4*)(g_adst + gid * 4);

    float sm[4] = {0.f, 0.f, 0.f, 0.f};
    float c0[4] = {0.f, 0.f, 0.f, 0.f};
    int s0 = 0;
    int e0 = rs + lane;
    for (int e = e0; e < re; e += 32) {
        int s = g_esrc[e];
        float4 av = *(const float4*)(g_asrc + (s * BT + bt) * 4);
        float v0 = __expf(lrelu(av.x + adv.x));
        float v1 = __expf(lrelu(av.y + adv.y));
        float v2 = __expf(lrelu(av.z + adv.z));
        float v3 = __expf(lrelu(av.w + adv.w));
        sm[0] += v0; sm[1] += v1; sm[2] += v2; sm[3] += v3;
        if (e == e0) { s0 = s; c0[0] = v0; c0[1] = v1; c0[2] = v2; c0[3] = v3; }
    }
    #pragma unroll
    for (int o = 16; o; o >>= 1) {
        #pragma unroll
        for (int h = 0; h < 4; h++) sm[h] += __shfl_xor_sync(full, sm[h], o);
    }
    float inv[4];
    #pragma unroll
    for (int h = 0; h < 4; h++) inv[h] = 1.f / (sm[h] + 1e-16f);
    if (e0 < re) {
        s_src[w][lane] = s0;
        #pragma unroll
        for (int h = 0; h < 4; h++) {
            float c = c0[h] * inv[h];
            s_cf[w][lane][h] = pack2(c, c);
        }
    }
    __syncwarp();

    ull acc0 = 0, acc1 = 0, acc2 = 0, acc3 = 0;
    const float* xb = x + (size_t)bt * (Nn * 64);
    int deg = re - rs;
    int jm = deg < 32 ? deg : 32;
    int j = 0;
    for (; j + 2 <= jm; j += 2) {          // 2-way unroll: explicit MLP on x gathers
        int sA = s_src[w][j];
        int sB = s_src[w][j + 1];
        ull xv1 = *(const ull*)(xb + sA * 64 + 2 * lane);
        ull xv2 = *(const ull*)(xb + sB * 64 + 2 * lane);
        ulonglong2 cA1 = *(const ulonglong2*)&s_cf[w][j][0];
        ulonglong2 cB1 = *(const ulonglong2*)&s_cf[w][j][2];
        ulonglong2 cA2 = *(const ulonglong2*)&s_cf[w][j + 1][0];
        ulonglong2 cB2 = *(const ulonglong2*)&s_cf[w][j + 1][2];
        ffma2(acc0, xv1, cA1.x);
        ffma2(acc1, xv1, cA1.y);
        ffma2(acc2, xv1, cB1.x);
        ffma2(acc3, xv1, cB1.y);
        ffma2(acc0, xv2, cA2.x);
        ffma2(acc1, xv2, cA2.y);
        ffma2(acc2, xv2, cB2.x);
        ffma2(acc3, xv2, cB2.y);
    }
    if (j < jm) {
        int src = s_src[w][j];
        ulonglong2 cA = *(const ulonglong2*)&s_cf[w][j][0];
        ulonglong2 cB = *(const ulonglong2*)&s_cf[w][j][2];
        ull xv = *(const ull*)(xb + src * 64 + 2 * lane);
        ffma2(acc0, xv, cA.x);
        ffma2(acc1, xv, cA.y);
        ffma2(acc2, xv, cB.x);
        ffma2(acc3, xv, cB.y);
    }
    for (int jj = 32; jj < deg; jj++) {    // rare: degree > 32
        int src = g_esrc[rs + jj];
        float4 av = *(const float4*)(g_asrc + (src * BT + bt) * 4);
        float cc0 = __expf(lrelu(av.x + adv.x)) * inv[0];
        float cc1 = __expf(lrelu(av.y + adv.y)) * inv[1];
        float cc2 = __expf(lrelu(av.z + adv.z)) * inv[2];
        float cc3 = __expf(lrelu(av.w + adv.w)) * inv[3];
        ull xv = *(const ull*)(xb + src * 64 + 2 * lane);
        ffma2(acc0, xv, pack2(cc0, cc0));
        ffma2(acc1, xv, pack2(cc1, cc1));
        ffma2(acc2, xv, pack2(cc2, cc2));
        ffma2(acc3, xv, pack2(cc3, cc3));
    }
    size_t base = (size_t)gid * 128 + lane;    // bf162 index: k = h*64 + 2*lane
    __nv_bfloat162* ah = ((__nv_bfloat162*)g_Ahi) + base;
    __nv_bfloat162* al = ((__nv_bfloat162*)g_Alo) + base;
    split_store(acc0, ah, al, 0);
    split_store(acc1, ah, al, 32);
    split_store(acc2, ah, al, 64);
    split_store(acc3, ah, al, 96);
}

// ---------------- K3: persistent pipelined WMMA GEMM + fused LN ----------------
// 325 blocks x 3 tiles of 64 rows (975 tiles = NBT/64 exactly). 128 threads,
// 4 warps, warp = 16 rows. Continuous cp.async double-buffer across ALL 12
// chunks (3 tiles x 4 K-chunks); epilogue CS aliases the just-consumed A buf
// so the pipeline never drains until block end. Single wave (3 blocks/SM).
#define TILES_PER_BLK 3
#define NBLK 325
#define GBM 64
#define LDA 72
#define A_BUF (GBM * LDA)                 // 4608 bf16 per matrix per buffer
#define B_BUF (64 * LDA)                  // 4608 bf16
#define OFF_AH(b) ((b) * 2 * A_BUF)
#define OFF_AL(b) ((b) * 2 * A_BUF + A_BUF)
#define OFF_BH(b) (4 * A_BUF + (b) * 2 * B_BUF)
#define OFF_BL(b) (4 * A_BUF + (b) * 2 * B_BUF + B_BUF)
#define GEMM_SMEM_BYTES ((4 * A_BUF + 4 * B_BUF) * 2)   // 73728

__device__ __forceinline__ void stage_chunk64(uint32_t sb, int buf,
                                              int r0, int kc, int tid) {
    // A: 1024 x 16B (hi+lo) for 64 rows x 64 k
    #pragma unroll
    for (int i = 0; i < 8; i++) {
        int idx = tid + 128 * i;
        int m = idx >> 9;
        int v = idx & 511;
        int row = v >> 3;
        int k8 = (v & 7) * 8;
        const __nv_bfloat16* src = (m ? g_Alo : g_Ahi) + (size_t)(r0 + row) * 256 + kc + k8;
        uint32_t dst = sb + ((m ? OFF_AL(buf) : OFF_AH(buf)) + row * LDA + k8) * 2;
        CP_CG16(dst, src);
    }
    // B: 1024 x 16B (hi+lo) for 64 k x 64 f
    #pragma unroll
    for (int i = 0; i < 8; i++) {
        int idx = tid + 128 * i;
        int m = idx >> 9;
        int v = idx & 511;
        int row = v >> 3;
        int f0 = (v & 7) * 8;
        const __nv_bfloat16* src = (m ? g_Bl : g_Bh) + (size_t)(kc + row) * 64 + f0;
        uint32_t dst = sb + ((m ? OFF_BL(buf) : OFF_BH(buf)) + row * LDA + f0) * 2;
        CP_CA16(dst, src);
    }
    CP_COMMIT();
}

__global__ __launch_bounds__(128) void k_gemm(const float* __restrict__ x,
                                              const float* __restrict__ bias,
                                              const float* __restrict__ gamma,
                                              const float* __restrict__ beta,
                                              float* __restrict__ out) {
    extern __shared__ __align__(16) __nv_bfloat16 sm_bf[];
    uint32_t sb = smem_u32(sm_bf);
    int tid = threadIdx.x;
    int w = tid >> 5, lane = tid & 31;

    wmma::fragment<wmma::accumulator, 16, 16, 16, float> acc[4];
    #pragma unroll
    for (int c = 0; c < 4; c++) wmma::fill_fragment(acc[c], 0.f);

    float2 bi = ((const float2*)bias)[lane];
    float2 ga = ((const float2*)gamma)[lane];
    float2 be = ((const float2*)beta)[lane];
    const unsigned full = 0xffffffffu;

    // global chunk id g in [0, 12): tile = g>>2, kc = (g&3)*64
    // tile t of this block covers rows (blockIdx.x + NBLK*t) * 64
    int r0_0 = blockIdx.x * GBM;               // tile 0 rows
    stage_chunk64(sb, 0, r0_0, 0, tid);

    #pragma unroll 1
    for (int g = 0; g < 4 * TILES_PER_BLK; g++) {
        int cur = g & 1;
        if (g < 4 * TILES_PER_BLK - 1) {
            int gn = g + 1;
            int rn = (blockIdx.x + NBLK * (gn >> 2)) * GBM;
            stage_chunk64(sb, 1 - cur, rn, (gn & 3) * 64, tid);
            asm volatile("cp.async.wait_group 1;" ::: "memory");
        } else {
            asm volatile("cp.async.wait_group 0;" ::: "memory");
        }
        __syncthreads();

        const __nv_bfloat16* Ah = sm_bf + OFF_AH(cur);
        const __nv_bfloat16* Al = sm_bf + OFF_AL(cur);
        const __nv_bfloat16* Bh = sm_bf + OFF_BH(cur);
        const __nv_bfloat16* Bl = sm_bf + OFF_BL(cur);
        #pragma unroll
        for (int ks = 0; ks < 4; ks++) {
            wmma::fragment<wmma::matrix_a, 16, 16, 16, __nv_bfloat16, wmma::row_major> fah, fal;
            wmma::load_matrix_sync(fah, Ah + (w * 16) * LDA + ks * 16, LDA);
            wmma::load_matrix_sync(fal, Al + (w * 16) * LDA + ks * 16, LDA);
            #pragma unroll
            for (int cc = 0; cc < 4; cc++) {
                wmma::fragment<wmma::matrix_b, 16, 16, 16, __nv_bfloat16, wmma::row_major> fbh, fbl;
                wmma::load_matrix_sync(fbh, Bh + (ks * 16) * LDA + cc * 16, LDA);
                wmma::load_matrix_sync(fbl, Bl + (ks * 16) * LDA + cc * 16, LDA);
                wmma::mma_sync(acc[cc], fah, fbh, acc[cc]);
                wmma::mma_sync(acc[cc], fah, fbl, acc[cc]);
                wmma::mma_sync(acc[cc], fal, fbh, acc[cc]);
            }
        }
        __syncthreads();

        if ((g & 3) == 3) {
            // ---- tile done: epilogue. CS aliases the just-consumed A buf ----
            int tile = g >> 2;
            int r0 = (blockIdx.x + NBLK * tile) * GBM;
            float* CS = (float*)(sm_bf + OFF_AH(cur));   // 18432B >= 64*64*4
            #pragma unroll
            for (int c = 0; c < 4; c++)
                wmma::store_matrix_sync(CS + (w * 16) * 64 + c * 16, acc[c], 64,
                                        wmma::mem_row_major);
            #pragma unroll
            for (int c = 0; c < 4; c++) wmma::fill_fragment(acc[c], 0.f);
            __syncthreads();
            #pragma unroll
            for (int it = 0; it < 16; it++) {
                int row = w * 16 + it;
                int r = r0 + row;
                int n = r / BT, bt = r % BT;
                size_t xo = ((size_t)bt * Nn + n) * 64;
                float2 cc = *(const float2*)(CS + row * 64 + lane * 2);
                float2 xv = *(const float2*)(x + xo + lane * 2);
                float yx = xv.x + cc.x + bi.x;
                float yy = xv.y + cc.y + bi.y;
                float s = yx + yy;
                float s2 = yx * yx + yy * yy;
                #pragma unroll
                for (int o = 16; o; o >>= 1) {
                    s += __shfl_xor_sync(full, s, o);
                    s2 += __shfl_xor_sync(full, s2, o);
                }
                float mu = s * (1.f / 64.f);
                float var = s2 * (1.f / 64.f) - mu * mu;
                float rstd = rsqrtf(var + 1e-5f);
                float2 o2;
                o2.x = (yx - mu) * rstd * ga.x + be.x;
                o2.y = (yy - mu) * rstd * ga.y + be.y;
                *(float2*)(out + xo + lane * 2) = o2;
            }
            __syncthreads();   // CS region free before it is restaged
        }
    }
}

// ---------------- launcher ----------------
extern "C" void kernel_launch(void* const* d_in, const int* in_sizes, int n_in,
                              void* d_out, int out_size) {
    const float* x        = (const float*)d_in[0];
    const float* W        = (const float*)d_in[1];
    const float* att_src  = (const float*)d_in[2];
    const float* att_dst  = (const float*)d_in[3];
    const float* bias     = (const float*)d_in[4];
    const float* gamma    = (const float*)d_in[5];
    const float* beta     = (const float*)d_in[6];
    const int*   edge     = (const int*)d_in[7];
    float* out = (float*)d_out;

    static bool attr_set = false;
    if (!attr_set) {
        cudaFuncSetAttribute(k_gemm, cudaFuncAttributeMaxDynamicSharedMemorySize,
                             GEMM_SMEM_BYTES);
        attr_set = true;
    }
    k_setup<<<2, 1024>>>(edge, W, att_src, att_dst);
    k_alpha<<<NBT / 8, 256>>>(x);
    k_agg<<<NBT / 8, 256>>>(x);
    k_gemm<<<NBLK, 128, GEMM_SMEM_BYTES>>>(x, bias, gamma, beta, out);
}

// round 15
// speedup vs baseline: 1.3160x; 1.3160x over previous
#include <cuda_runtime.h>
#include <cuda_fp16.h>
#include <mma.h>
#include <cstdint>

using namespace nvcuda;

#define Bn 16
#define Tn 12
#define BT 192          // B*T
#define Nn 325
#define Dd 64
#define Hh 4
#define Ee 2600
#define ET (Ee + Nn)    // 2925 edges incl. self loops
#define NBT (Nn * BT)   // 62400 (n,bt) pairs

typedef unsigned long long ull;

// ---------------- packed f32x2 helpers ----------------
__device__ __forceinline__ void ffma2(ull& d, ull a, ull b) {
    asm("fma.rn.f32x2 %0, %1, %2, %0;" : "+l"(d) : "l"(a), "l"(b));
}
__device__ __forceinline__ ull pack2(float lo, float hi) {
    ull r; asm("mov.b64 %0, {%1,%2};" : "=l"(r) : "f"(lo), "f"(hi)); return r;
}
__device__ __forceinline__ void unpack2(float& lo, float& hi, ull v) {
    asm("mov.b64 {%0,%1}, %2;" : "=f"(lo), "=f"(hi) : "l"(v));
}
__device__ __forceinline__ uint32_t smem_u32(const void* p) {
    uint32_t a;
    asm("{.reg .u64 t; cvta.to.shared.u64 t, %1; cvt.u32.u64 %0, t;}" : "=r"(a) : "l"(p));
    return a;
}
#define CP_CG16(dst_u32, src_ptr) \
    asm volatile("cp.async.cg.shared.global [%0], [%1], 16;" \
                 :: "r"(dst_u32), "l"(src_ptr) : "memory")
#define CP_CA16(dst_u32, src_ptr) \
    asm volatile("cp.async.ca.shared.global [%0], [%1], 16;" \
                 :: "r"(dst_u32), "l"(src_ptr) : "memory")
#define CP_COMMIT() asm volatile("cp.async.commit_group;" ::: "memory")

// ---------------- device scratch ----------------
__device__ __align__(16) float g_wsrc[Hh * Dd];
__device__ __align__(16) float g_wdst[Hh * Dd];
__device__ __align__(16) float g_asrc[NBT * Hh];
__device__ __align__(16) float g_adst[NBT * Hh];
__device__ int g_rowptr[Nn + 1];
__device__ int g_esrc[ET];
__device__ __align__(16) __half g_Af[(size_t)NBT * 256];   // fp16 A, 32MB
__device__ __align__(16) __half g_Bh[256 * 64];            // B hi fp16, [k][f], 1/H folded
__device__ __align__(16) __half g_Bl[256 * 64];            // B lo fp16 (residual)

// ---------------- K0: setup (block 0 = CSR, block 1 = weight prep) ----------------
// edge_index may be int32 or int64 (JAX x64-config). Probe: int64 => every odd
// 32-bit word in the first 5200 words is 0 (values < 325).
__global__ void k_setup(const int* __restrict__ ew,
                        const float* __restrict__ W,
                        const float* __restrict__ att_src,
                        const float* __restrict__ att_dst) {
    int tid = threadIdx.x;
    int bd = blockDim.x;      // 1024
    const unsigned full = 0xffffffffu;
    if (blockIdx.x == 1) {
        if (tid < 256) {
            int h = tid >> 6, d = tid & 63;
            float s1 = 0.f, s2 = 0.f;
            #pragma unroll 8
            for (int f = 0; f < 64; f++) {
                float w = W[(d * Hh + h) * 64 + f];
                s1 += w * att_src[h * 64 + f];
                s2 += w * att_dst[h * 64 + f];
            }
            g_wsrc[tid] = s1;
            g_wdst[tid] = s2;
        }
        for (int i = tid; i < 256 * 64; i += bd) {
            int k = i >> 6, f = i & 63;
            int h = k >> 6, d = k & 63;
            float w = W[(d * Hh + h) * 64 + f] * 0.25f;   // 1/H folded
            __half hi = __float2half_rn(w);
            g_Bh[i] = hi;
            g_Bl[i] = __float2half_rn(w - __half2float(hi));
        }
        return;
    }
    // ---- CSR build, deterministic (sorted by original edge id) ----
    __shared__ int sdst[ET];
    __shared__ int ssrc[ET];
    __shared__ int sslot[ET];
    __shared__ int scnt[Nn + 1];
    __shared__ int scur[Nn];
    __shared__ int s_is32;
    if (tid == 0) s_is32 = 0;
    __syncthreads();
    for (int i = tid; i < Ee; i += bd)
        if (ew[2 * i + 1] != 0) s_is32 = 1;
    __syncthreads();
    int is32 = s_is32;
    for (int i = tid; i < ET; i += bd) {
        if (i < Ee) {
            if (is32) { ssrc[i] = ew[i];         sdst[i] = ew[Ee + i]; }
            else      { ssrc[i] = ew[2 * i];     sdst[i] = ew[2 * (Ee + i)]; }
        } else {
            ssrc[i] = i - Ee;
            sdst[i] = i - Ee;
        }
    }
    for (int i = tid; i <= Nn; i += bd) scnt[i] = 0;
    __syncthreads();
    for (int i = tid; i < ET; i += bd) atomicAdd(&scnt[sdst[i] + 1], 1);
    __syncthreads();
    if (tid < 32) {            // warp-parallel inclusive scan
        int carry = 0;
        for (int base = 0; base <= Nn; base += 32) {
            int i = base + tid;
            int v = (i <= Nn) ? scnt[i] : 0;
            #pragma unroll
            for (int o = 1; o < 32; o <<= 1) {
                int t = __shfl_up_sync(full, v, o);
                if (tid >= o) v += t;
            }
            v += carry;
            if (i <= Nn) scnt[i] = v;
            carry = __shfl_sync(full, v, 31);
        }
    }
    __syncthreads();
    for (int i = tid; i <= Nn; i += bd) g_rowptr[i] = scnt[i];
    for (int i = tid; i < Nn; i += bd) scur[i] = scnt[i];
    __syncthreads();
    for (int e = tid; e < ET; e += bd) {
        int pos = atomicAdd(&scur[sdst[e]], 1);
        sslot[pos] = e;
    }
    __syncthreads();
    for (int n = tid; n < Nn; n += bd) {
        int a = scnt[n], b = scnt[n + 1];
        for (int i = a + 1; i < b; i++) {      // sort by edge id -> deterministic
            int v = sslot[i];
            int j = i - 1;
            while (j >= a && sslot[j] > v) { sslot[j + 1] = sslot[j]; j--; }
            sslot[j + 1] = v;
        }
        for (int p = a; p < b; p++) g_esrc[p] = ssrc[sslot[p]];
    }
}

// ---------------- K1: attention logits, warp per (n,bt) ----------------
__global__ __launch_bounds__(256) void k_alpha(const float* __restrict__ x) {
    __shared__ float sw[512];
    int tid = threadIdx.x;
    sw[tid] = g_wsrc[tid];
    sw[256 + tid] = g_wdst[tid];
    __syncthreads();
    int gid = blockIdx.x * 8 + (tid >> 5);
    int lane = tid & 31;
    int n = gid / BT, bt = gid % BT;
    float2 xv = ((const float2*)(x + ((size_t)bt * Nn + n) * 64))[lane];
    float p[8];
    #pragma unroll
    for (int h = 0; h < 4; h++) {
        p[h]     = xv.x * sw[h * 64 + 2 * lane]       + xv.y * sw[h * 64 + 2 * lane + 1];
        p[4 + h] = xv.x * sw[256 + h * 64 + 2 * lane] + xv.y * sw[256 + h * 64 + 2 * lane + 1];
    }
    #pragma unroll
    for (int o = 16; o; o >>= 1) {
        #pragma unroll
        for (int j = 0; j < 8; j++) p[j] += __shfl_xor_sync(0xffffffffu, p[j], o);
    }
    int base = gid * 4;
    if (lane < 4) g_asrc[base + lane] = p[lane];
    else if (lane < 8) g_adst[base + lane - 4] = p[lane];
}

// ---------------- K2: segment softmax + aggregation -> fp16 A ----------------
__device__ __forceinline__ float lrelu(float v) { return v >= 0.f ? v : 0.2f * v; }

__global__ __launch_bounds__(256) void k_agg(const float* __restrict__ x) {
    __shared__ int s_src[8][32];
    __shared__ __align__(16) ull s_cf[8][32][4];   // dup'd coef pairs {c,c}
    const unsigned full = 0xffffffffu;
    int tid = threadIdx.x;
    int w = tid >> 5, lane = tid & 31;
    int gid = blockIdx.x * 8 + w;
    int n = gid / BT, bt = gid % BT;
    int rs = g_rowptr[n], re = g_rowptr[n + 1];
    float4 adv = *(const float4*)(g_adst + gid * 4);

    float sm[4] = {0.f, 0.f, 0.f, 0.f};
    float c0[4] = {0.f, 0.f, 0.f, 0.f};
    int s0 = 0;
    int e0 = rs + lane;
    for (int e = e0; e < re; e += 32) {
        int s = g_esrc[e];
        float4 av = *(const float4*)(g_asrc + (s * BT + bt) * 4);
        float v0 = __expf(lrelu(av.x + adv.x));
        float v1 = __expf(lrelu(av.y + adv.y));
        float v2 = __expf(lrelu(av.z + adv.z));
        float v3 = __expf(lrelu(av.w + adv.w));
        sm[0] += v0; sm[1] += v1; sm[2] += v2; sm[3] += v3;
        if (e == e0) { s0 = s; c0[0] = v0; c0[1] = v1; c0[2] = v2; c0[3] = v3; }
    }
    #pragma unroll
    for (int o = 16; o; o >>= 1) {
        #pragma unroll
        for (int h = 0; h < 4; h++) sm[h] += __shfl_xor_sync(full, sm[h], o);
    }
    float inv[4];
    #pragma unroll
    for (int h = 0; h < 4; h++) inv[h] = 1.f / (sm[h] + 1e-16f);
    if (e0 < re) {
        s_src[w][lane] = s0;
        #pragma unroll
        for (int h = 0; h < 4; h++) {
            float c = c0[h] * inv[h];
            s_cf[w][lane][h] = pack2(c, c);
        }
    }
    __syncwarp();

    ull acc0 = 0, acc1 = 0, acc2 = 0, acc3 = 0;
    const float* xb = x + (size_t)bt * (Nn * 64);
    int deg = re - rs;
    int jm = deg < 32 ? deg : 32;
    int j = 0;
    for (; j + 2 <= jm; j += 2) {          // 2-way unroll: explicit MLP on x gathers
        int sA = s_src[w][j];
        int sB = s_src[w][j + 1];
        ull xv1 = *(const ull*)(xb + sA * 64 + 2 * lane);
        ull xv2 = *(const ull*)(xb + sB * 64 + 2 * lane);
        ulonglong2 cA1 = *(const ulonglong2*)&s_cf[w][j][0];
        ulonglong2 cB1 = *(const ulonglong2*)&s_cf[w][j][2];
        ulonglong2 cA2 = *(const ulonglong2*)&s_cf[w][j + 1][0];
        ulonglong2 cB2 = *(const ulonglong2*)&s_cf[w][j + 1][2];
        ffma2(acc0, xv1, cA1.x);
        ffma2(acc1, xv1, cA1.y);
        ffma2(acc2, xv1, cB1.x);
        ffma2(acc3, xv1, cB1.y);
        ffma2(acc0, xv2, cA2.x);
        ffma2(acc1, xv2, cA2.y);
        ffma2(acc2, xv2, cB2.x);
        ffma2(acc3, xv2, cB2.y);
    }
    if (j < jm) {
        int src = s_src[w][j];
        ulonglong2 cA = *(const ulonglong2*)&s_cf[w][j][0];
        ulonglong2 cB = *(const ulonglong2*)&s_cf[w][j][2];
        ull xv = *(const ull*)(xb + src * 64 + 2 * lane);
        ffma2(acc0, xv, cA.x);
        ffma2(acc1, xv, cA.y);
        ffma2(acc2, xv, cB.x);
        ffma2(acc3, xv, cB.y);
    }
    for (int jj = 32; jj < deg; jj++) {    // rare: degree > 32
        int src = g_esrc[rs + jj];
        float4 av = *(const float4*)(g_asrc + (src * BT + bt) * 4);
        float cc0 = __expf(lrelu(av.x + adv.x)) * inv[0];
        float cc1 = __expf(lrelu(av.y + adv.y)) * inv[1];
        float cc2 = __expf(lrelu(av.z + adv.z)) * inv[2];
        float cc3 = __expf(lrelu(av.w + adv.w)) * inv[3];
        ull xv = *(const ull*)(xb + src * 64 + 2 * lane);
        ffma2(acc0, xv, pack2(cc0, cc0));
        ffma2(acc1, xv, pack2(cc1, cc1));
        ffma2(acc2, xv, pack2(cc2, cc2));
        ffma2(acc3, xv, pack2(cc3, cc3));
    }
    // store fp16 A: half2 index, k = h*64 + 2*lane
    size_t base = (size_t)gid * 128 + lane;
    __half2* af = ((__half2*)g_Af) + base;
    float e, o;
    unpack2(e, o, acc0); af[0]  = __floats2half2_rn(e, o);
    unpack2(e, o, acc1); af[32] = __floats2half2_rn(e, o);
    unpack2(e, o, acc2); af[64] = __floats2half2_rn(e, o);
    unpack2(e, o, acc3); af[96] = __floats2half2_rn(e, o);
}

// ---------------- K3: fp16 WMMA GEMM, cp.async double-buffered + fused LN ----------------
// Block: 96 rows x 64 cols, K=256 in 4 chunks of 64. 192 threads = 6 warps,
// warp = 16 rows. D = A*(Bh) + A*(Bl), f32 accum. 650 blocks exact.
#define GBM 96
#define LDA 72
#define A_BUF (GBM * LDA)                 // 6912 half
#define B_BUF (64 * LDA)                  // 4608 half
#define OFF_A(b)  ((b) * A_BUF)
#define OFF_BH(b) (2 * A_BUF + (b) * 2 * B_BUF)
#define OFF_BL(b) (2 * A_BUF + (b) * 2 * B_BUF + B_BUF)
#define GEMM_SMEM_BYTES ((2 * A_BUF + 4 * B_BUF) * 2)   // 64512

__device__ __forceinline__ void stage_chunk(uint32_t sb, int buf,
                                            int r0, int kc, int tid) {
    // A: 768 x 16B for 96 rows x 64 k (fp16)
    #pragma unroll
    for (int i = 0; i < 4; i++) {
        int idx = tid + 192 * i;
        int row = idx >> 3;
        int k8 = (idx & 7) * 8;
        const __half* src = g_Af + (size_t)(r0 + row) * 256 + kc + k8;
        uint32_t dst = sb + (OFF_A(buf) + row * LDA + k8) * 2;
        CP_CG16(dst, src);
    }
    // B hi+lo: 1024 x 16B for 64 k x 64 f
    #pragma unroll
    for (int i = 0; i < 6; i++) {
        int idx = tid + 192 * i;
        if (idx < 1024) {
            int m = idx >> 9;
            int v = idx & 511;
            int row = v >> 3;
            int f0 = (v & 7) * 8;
            const __half* src = (m ? g_Bl : g_Bh) + (size_t)(kc + row) * 64 + f0;
            uint32_t dst = sb + ((m ? OFF_BL(buf) : OFF_BH(buf)) + row * LDA + f0) * 2;
            CP_CA16(dst, src);
        }
    }
    CP_COMMIT();
}

__global__ __launch_bounds__(192) void k_gemm(const float* __restrict__ x,
                                              const float* __restrict__ bias,
                                              const float* __restrict__ gamma,
                                              const float* __restrict__ beta,
                                              float* __restrict__ out) {
    extern __shared__ __align__(16) __half sm_h[];
    uint32_t sb = smem_u32(sm_h);
    float* CS = (float*)sm_h;                 // epilogue alias (24KB <= 2*A_BUF*2)
    int tid = threadIdx.x;
    int w = tid >> 5, lane = tid & 31;
    int r0 = blockIdx.x * GBM;

    wmma::fragment<wmma::accumulator, 16, 16, 16, float> acc[4];
    #pragma unroll
    for (int c = 0; c < 4; c++) wmma::fill_fragment(acc[c], 0.f);

    stage_chunk(sb, 0, r0, 0, tid);

    #pragma unroll 1
    for (int c = 0; c < 4; c++) {
        int cur = c & 1;
        if (c < 3) {
            stage_chunk(sb, 1 - cur, r0, (c + 1) * 64, tid);
            asm volatile("cp.async.wait_group 1;" ::: "memory");
        } else {
            asm volatile("cp.async.wait_group 0;" ::: "memory");
        }
        __syncthreads();

        const __half* As = sm_h + OFF_A(cur);
        const __half* Bh = sm_h + OFF_BH(cur);
        const __half* Bl = sm_h + OFF_BL(cur);
        #pragma unroll
        for (int ks = 0; ks < 4; ks++) {
            wmma::fragment<wmma::matrix_a, 16, 16, 16, half, wmma::row_major> fa;
            wmma::load_matrix_sync(fa, As + (w * 16) * LDA + ks * 16, LDA);
            #pragma unroll
            for (int cc = 0; cc < 4; cc++) {
                wmma::fragment<wmma::matrix_b, 16, 16, 16, half, wmma::row_major> fbh, fbl;
                wmma::load_matrix_sync(fbh, Bh + (ks * 16) * LDA + cc * 16, LDA);
                wmma::load_matrix_sync(fbl, Bl + (ks * 16) * LDA + cc * 16, LDA);
                wmma::mma_sync(acc[cc], fa, fbh, acc[cc]);
                wmma::mma_sync(acc[cc], fa, fbl, acc[cc]);
            }
        }
        __syncthreads();
    }

    // ---- stage C into shared ----
    #pragma unroll
    for (int c = 0; c < 4; c++)
        wmma::store_matrix_sync(CS + (w * 16) * 64 + c * 16, acc[c], 64, wmma::mem_row_major);
    __syncthreads();

    // ---- epilogue: bias + residual + LayerNorm, warp per row, 16 rows/warp ----
    float2 bi = ((const float2*)bias)[lane];
    float2 ga = ((const float2*)gamma)[lane];
    float2 be = ((const float2*)beta)[lane];
    const unsigned full = 0xffffffffu;
    #pragma unroll
    for (int it = 0; it < 16; it++) {
        int row = w * 16 + it;
        int r = r0 + row;
        int n = r / BT, bt = r % BT;
        size_t xo = ((size_t)bt * Nn + n) * 64;
        float2 cc = *(const float2*)(CS + row * 64 + lane * 2);
        float2 xv = *(const float2*)(x + xo + lane * 2);
        float yx = xv.x + cc.x + bi.x;
        float yy = xv.y + cc.y + bi.y;
        float s = yx + yy;
        float s2 = yx * yx + yy * yy;
        #pragma unroll
        for (int o = 16; o; o >>= 1) {
            s += __shfl_xor_sync(full, s, o);
            s2 += __shfl_xor_sync(full, s2, o);
        }
        float mu = s * (1.f / 64.f);
        float var = s2 * (1.f / 64.f) - mu * mu;
        float rstd = rsqrtf(var + 1e-5f);
        float2 o2;
        o2.x = (yx - mu) * rstd * ga.x + be.x;
        o2.y = (yy - mu) * rstd * ga.y + be.y;
        *(float2*)(out + xo + lane * 2) = o2;
    }
}

// ---------------- launcher ----------------
extern "C" void kernel_launch(void* const* d_in, const int* in_sizes, int n_in,
                              void* d_out, int out_size) {
    const float* x        = (const float*)d_in[0];
    const float* W        = (const float*)d_in[1];
    const float* att_src  = (const float*)d_in[2];
    const float* att_dst  = (const float*)d_in[3];
    const float* bias     = (const float*)d_in[4];
    const float* gamma    = (const float*)d_in[5];
    const float* beta     = (const float*)d_in[6];
    const int*   edge     = (const int*)d_in[7];
    float* out = (float*)d_out;

    static bool attr_set = false;
    if (!attr_set) {
        cudaFuncSetAttribute(k_gemm, cudaFuncAttributeMaxDynamicSharedMemorySize,
                             GEMM_SMEM_BYTES);
        attr_set = true;
    }
    k_setup<<<2, 1024>>>(edge, W, att_src, att_dst);
    k_alpha<<<NBT / 8, 256>>>(x);
    k_agg<<<NBT / 8, 256>>>(x);
    k_gemm<<<NBT / GBM, 192, GEMM_SMEM_BYTES>>>(x, bias, gamma, beta, out);
}